// round 2
// baseline (speedup 1.0000x reference)
#include <cuda_runtime.h>
#include <cuda_bf16.h>
#include <math.h>

#define S   768
#define CS  384
#define CP  128
#define E   16
#define PQ  4
#define PV  8
#define H   12
#define NCOL 1152            // per-residue projection columns: H*96
#define FOUT 2112            // H*(CP+E+PV*4)

#define SCALE_SINGLE 0.25f   // 1/sqrt(16)
// scale_frame = -1/sqrt(18*PQ) = -1/sqrt(72)
#define SCALE_FRAME (-0.11785113019775793f)

// ---------------- scratch (static device globals; no allocations) ----------------
__device__ float g_raw[S * NCOL];          // raw projections [s][1152]
__device__ float g_Qcat[H * S * 28];       // [0.25*q(16) | -2c_h*lqp(12)]
__device__ float g_Kcat[H * S * 28];       // [k(16) | lkp(12)]
__device__ float g_Vcat[H * S * 40];       // [v(16) | lvp(24)]
__device__ float g_qn[H * S];              // c_h * sum_p |lqp|^2
__device__ float g_kn[H * S];              // c_h * sum_p |lkp|^2
__device__ float g_a[H * S * S];           // logits, then softmax in place (28.3MB)
__device__ float g_asum[H * S];
__device__ float g_ol[H * S * PV * 3];
__device__ float g_attn[S * FOUT];         // concat features

// ---------------- kernel 1: projection GEMM  x[S,384] @ W^T -> raw[S,1152] ---------
__device__ __forceinline__ const float* colptr(int j,
    const float* Wq, const float* Wk, const float* Wv,
    const float* Wqp, const float* Wkp, const float* Wvp) {
    int h = j / 96, off = j % 96;
    if (off < 16) return Wq  + (h * 16 + off) * CS;
    if (off < 32) return Wk  + (h * 16 + off - 16) * CS;
    if (off < 48) return Wv  + (h * 16 + off - 32) * CS;
    if (off < 60) return Wqp + (h * 12 + off - 48) * CS;
    if (off < 72) return Wkp + (h * 12 + off - 60) * CS;
    return Wvp + (h * 24 + off - 72) * CS;
}

__global__ void __launch_bounds__(256) k_proj(const float* __restrict__ x,
    const float* __restrict__ Wq, const float* __restrict__ Wk, const float* __restrict__ Wv,
    const float* __restrict__ Wqp, const float* __restrict__ Wkp, const float* __restrict__ Wvp) {
    __shared__ float xs[16 * CS];   // 24 KB
    int s0 = blockIdx.x * 16;
    for (int idx = threadIdx.x; idx < 16 * CS; idx += 256)
        xs[idx] = x[s0 * CS + idx];
    __syncthreads();

    for (int j0 = threadIdx.x * 2; j0 < NCOL; j0 += 512) {
        const float* w0 = colptr(j0,     Wq, Wk, Wv, Wqp, Wkp, Wvp);
        const float* w1 = colptr(j0 + 1, Wq, Wk, Wv, Wqp, Wkp, Wvp);
        float acc0[16], acc1[16];
        #pragma unroll
        for (int s = 0; s < 16; s++) { acc0[s] = 0.f; acc1[s] = 0.f; }
        for (int kk = 0; kk < CS; kk += 4) {
            float4 wa = *(const float4*)(w0 + kk);
            float4 wb = *(const float4*)(w1 + kk);
            #pragma unroll
            for (int s = 0; s < 16; s++) {
                float4 xv = *(const float4*)&xs[s * CS + kk];
                acc0[s] += wa.x * xv.x + wa.y * xv.y + wa.z * xv.z + wa.w * xv.w;
                acc1[s] += wb.x * xv.x + wb.y * xv.y + wb.z * xv.z + wb.w * xv.w;
            }
        }
        #pragma unroll
        for (int s = 0; s < 16; s++) {
            g_raw[(s0 + s) * NCOL + j0]     = acc0[s];
            g_raw[(s0 + s) * NCOL + j0 + 1] = acc1[s];
        }
    }
}

// ---------------- kernel 2: frame apply + scale folding ----------------
__global__ void k_frames(const float* __restrict__ rot, const float* __restrict__ trans,
                         const float* __restrict__ gamma) {
    int idx = blockIdx.x * blockDim.x + threadIdx.x;
    if (idx >= H * S) return;
    int h = idx / S, s = idx % S;
    const float* R = rot + s * 9;
    float R00=R[0],R01=R[1],R02=R[2],R10=R[3],R11=R[4],R12=R[5],R20=R[6],R21=R[7],R22=R[8];
    float t0 = trans[s*3+0], t1 = trans[s*3+1], t2 = trans[s*3+2];
    float ch = SCALE_FRAME * log1pf(expf(gamma[h]));   // negative

    const float* raw = g_raw + s * NCOL + h * 96;
    float* qc = g_Qcat + (h * S + s) * 28;
    float* kc = g_Kcat + (h * S + s) * 28;
    float* vc = g_Vcat + (h * S + s) * 40;

    #pragma unroll
    for (int e = 0; e < 16; e++) {
        qc[e] = raw[e] * SCALE_SINGLE;
        kc[e] = raw[16 + e];
        vc[e] = raw[32 + e];
    }
    float qn = 0.f, kn = 0.f;
    float m2c = -2.f * ch;
    #pragma unroll
    for (int p = 0; p < 4; p++) {
        float x = raw[48+p*3], y = raw[48+p*3+1], z = raw[48+p*3+2];
        float lx = R00*x + R01*y + R02*z + t0;
        float ly = R10*x + R11*y + R12*z + t1;
        float lz = R20*x + R21*y + R22*z + t2;
        qc[16+p*3]   = lx * m2c;
        qc[16+p*3+1] = ly * m2c;
        qc[16+p*3+2] = lz * m2c;
        qn += lx*lx + ly*ly + lz*lz;

        x = raw[60+p*3]; y = raw[60+p*3+1]; z = raw[60+p*3+2];
        lx = R00*x + R01*y + R02*z + t0;
        ly = R10*x + R11*y + R12*z + t1;
        lz = R20*x + R21*y + R22*z + t2;
        kc[16+p*3]   = lx;
        kc[16+p*3+1] = ly;
        kc[16+p*3+2] = lz;
        kn += lx*lx + ly*ly + lz*lz;
    }
    #pragma unroll
    for (int p = 0; p < 8; p++) {
        float x = raw[72+p*3], y = raw[72+p*3+1], z = raw[72+p*3+2];
        vc[16+p*3]   = R00*x + R01*y + R02*z + t0;
        vc[16+p*3+1] = R10*x + R11*y + R12*z + t1;
        vc[16+p*3+2] = R20*x + R21*y + R22*z + t2;
    }
    g_qn[h * S + s] = ch * qn;
    g_kn[h * S + s] = ch * kn;
}

// ---------------- kernel 3: batched logit GEMM (K=28) + norm bias ----------------
__global__ void __launch_bounds__(256) k_logit() {
    __shared__ float Qs[64 * 29], Ks[64 * 29], qns[64], kns[64];
    int h = blockIdx.z, i0 = blockIdx.y * 64, j0 = blockIdx.x * 64;
    int t = threadIdx.x;
    for (int idx = t; idx < 64 * 28; idx += 256) {
        int r = idx / 28, c = idx % 28;
        Qs[r * 29 + c] = g_Qcat[(h * S + i0 + r) * 28 + c];
        Ks[r * 29 + c] = g_Kcat[(h * S + j0 + r) * 28 + c];
    }
    if (t < 64) { qns[t] = g_qn[h * S + i0 + t]; kns[t] = g_kn[h * S + j0 + t]; }
    __syncthreads();
    int tx = t % 16, ty = t / 16;
    float acc[4][4] = {};
    for (int k = 0; k < 28; k++) {
        float aq[4], bk[4];
        #pragma unroll
        for (int r = 0; r < 4; r++) {
            aq[r] = Qs[(ty * 4 + r) * 29 + k];
            bk[r] = Ks[(tx * 4 + r) * 29 + k];
        }
        #pragma unroll
        for (int r = 0; r < 4; r++)
            #pragma unroll
            for (int c = 0; c < 4; c++)
                acc[r][c] += aq[r] * bk[c];
    }
    #pragma unroll
    for (int r = 0; r < 4; r++)
        #pragma unroll
        for (int c = 0; c < 4; c++)
            g_a[((size_t)h * S + i0 + ty * 4 + r) * S + j0 + tx * 4 + c] =
                acc[r][c] + qns[ty * 4 + r] + kns[tx * 4 + c];
}

// ---------------- kernel 4: fused w_pair + softmax (streams pair once) ----------------
__global__ void __launch_bounds__(256) k_pairsm(const float* __restrict__ pair,
                                                const float* __restrict__ Wb) {
    __shared__ float wp[S * 13];        // 39936 B, stride 13 to dodge conflicts
    __shared__ float Wbs[H * CP];       // 6144 B
    __shared__ float red[40];
    int i = blockIdx.x, t = threadIdx.x, lane = t & 31, w = t >> 5;

    for (int idx = t; idx < H * CP; idx += 256) Wbs[idx] = Wb[idx];
    __syncthreads();

    // phase A: wp[j][h] = Wb[h] . pair[i,j,:]
    const float4* pbase = (const float4*)(pair + (size_t)i * S * CP);
    for (int j = w; j < S; j += 8) {
        float4 pv = pbase[j * 32 + lane];
        int c = lane * 4;
        float acc[H];
        #pragma unroll
        for (int h = 0; h < H; h++)
            acc[h] = pv.x * Wbs[h*CP + c] + pv.y * Wbs[h*CP + c + 1]
                   + pv.z * Wbs[h*CP + c + 2] + pv.w * Wbs[h*CP + c + 3];
        #pragma unroll
        for (int h = 0; h < H; h++) {
            float v = acc[h];
            v += __shfl_xor_sync(0xffffffffu, v, 16);
            v += __shfl_xor_sync(0xffffffffu, v, 8);
            v += __shfl_xor_sync(0xffffffffu, v, 4);
            v += __shfl_xor_sync(0xffffffffu, v, 2);
            v += __shfl_xor_sync(0xffffffffu, v, 1);
            acc[h] = v;
        }
        if (lane == 0) {
            #pragma unroll
            for (int h = 0; h < H; h++) wp[j * 13 + h] = acc[h];
        }
    }
    __syncthreads();

    // phase B: per-head add + softmax over j, in place in g_a
    for (int h = 0; h < H; h++) {
        float* row = g_a + ((size_t)h * S + i) * S;
        float v[3];
        float m = -1e30f;
        #pragma unroll
        for (int r = 0; r < 3; r++) {
            int j = t + r * 256;
            v[r] = row[j] + wp[j * 13 + h];
            m = fmaxf(m, v[r]);
        }
        #pragma unroll
        for (int off = 16; off; off >>= 1) m = fmaxf(m, __shfl_xor_sync(0xffffffffu, m, off));
        if (lane == 0) red[w] = m;
        __syncthreads();
        if (w == 0) {
            float mm = (lane < 8) ? red[lane] : -1e30f;
            #pragma unroll
            for (int off = 4; off; off >>= 1) mm = fmaxf(mm, __shfl_xor_sync(0xffffffffu, mm, off));
            if (lane == 0) red[32] = mm;
        }
        __syncthreads();
        m = red[32];
        float sum = 0.f;
        #pragma unroll
        for (int r = 0; r < 3; r++) { v[r] = __expf(v[r] - m); sum += v[r]; }
        #pragma unroll
        for (int off = 16; off; off >>= 1) sum += __shfl_xor_sync(0xffffffffu, sum, off);
        if (lane == 0) red[w] = sum;
        __syncthreads();
        if (w == 0) {
            float ss = (lane < 8) ? red[lane] : 0.f;
            #pragma unroll
            for (int off = 4; off; off >>= 1) ss += __shfl_xor_sync(0xffffffffu, ss, off);
            if (lane == 0) red[33] = ss;
        }
        __syncthreads();
        float inv = 1.f / red[33];
        #pragma unroll
        for (int r = 0; r < 3; r++) row[t + r * 256] = v[r] * inv;
        __syncthreads();
    }
}

// ---------------- kernel 5: a_sum[h,k] = sum_i a[h,i,k] ----------------
__global__ void __launch_bounds__(256) k_asum() {
    int h = blockIdx.y;
    int k = blockIdx.x * 256 + threadIdx.x;
    const float* base = g_a + (size_t)h * S * S + k;
    float s0 = 0.f, s1 = 0.f, s2 = 0.f, s3 = 0.f;
    for (int i = 0; i < S; i += 4) {
        s0 += base[(size_t)(i + 0) * S];
        s1 += base[(size_t)(i + 1) * S];
        s2 += base[(size_t)(i + 2) * S];
        s3 += base[(size_t)(i + 3) * S];
    }
    g_asum[h * S + k] = (s0 + s1) + (s2 + s3);
}

// ---------------- kernel 6: per-head A @ Vcat (S x S x 40) ----------------
__global__ void __launch_bounds__(128) k_av() {
    __shared__ float As[64 * 65];   // 16.6 KB
    __shared__ float Vs[64 * 41];   // 10.5 KB
    int h = blockIdx.y, i0 = blockIdx.x * 64;
    int t = threadIdx.x;
    int rg = t / 8, cg = t % 8;
    int m0 = rg * 4;
    float acc[4][5] = {};

    for (int kc = 0; kc < S; kc += 64) {
        __syncthreads();
        for (int idx = t; idx < 64 * 64; idx += 128) {
            int r = idx >> 6, k = idx & 63;
            As[r * 65 + k] = g_a[((size_t)h * S + i0 + r) * S + kc + k];
        }
        for (int idx = t; idx < 64 * 40; idx += 128) {
            int r = idx / 40, n = idx % 40;
            Vs[r * 41 + n] = g_Vcat[(h * S + kc + r) * 40 + n];
        }
        __syncthreads();
        for (int k = 0; k < 64; k++) {
            float a0 = As[(m0+0)*65 + k], a1 = As[(m0+1)*65 + k];
            float a2 = As[(m0+2)*65 + k], a3 = As[(m0+3)*65 + k];
            float vv[5];
            #pragma unroll
            for (int c = 0; c < 5; c++) vv[c] = Vs[k * 41 + cg + 8 * c];
            #pragma unroll
            for (int c = 0; c < 5; c++) {
                acc[0][c] += a0 * vv[c];
                acc[1][c] += a1 * vv[c];
                acc[2][c] += a2 * vv[c];
                acc[3][c] += a3 * vv[c];
            }
        }
    }
    #pragma unroll
    for (int r = 0; r < 4; r++) {
        int i = i0 + m0 + r;
        #pragma unroll
        for (int c = 0; c < 5; c++) {
            int n = cg + 8 * c;
            float val = acc[r][c];
            if (n < 16) g_attn[i * FOUT + h * 16 + n] = val;                // o_single
            else        g_ol[(h * S + i) * 24 + (n - 16)] = val;            // o_local
        }
    }
}

// ---------------- kernel 7: inverse frame, points + norms into attn ----------------
__global__ void k_invf(const float* __restrict__ rot, const float* __restrict__ trans) {
    int idx = blockIdx.x * blockDim.x + threadIdx.x;
    if (idx >= H * S) return;
    int h = idx / S, s = idx % S;
    const float* R = rot + s * 9;
    float R00=R[0],R01=R[1],R02=R[2],R10=R[3],R11=R[4],R12=R[5],R20=R[6],R21=R[7],R22=R[8];
    float t0 = trans[s*3+0], t1 = trans[s*3+1], t2 = trans[s*3+2];
    const float* ol = g_ol + (h * S + s) * 24;
    float* dst = g_attn + s * FOUT;
    #pragma unroll
    for (int p = 0; p < PV; p++) {
        float x = ol[p*3+0] - t0, y = ol[p*3+1] - t1, z = ol[p*3+2] - t2;
        float gx = R00*x + R10*y + R20*z;   // R^T (x - t)
        float gy = R01*x + R11*y + R21*z;
        float gz = R02*x + R12*y + R22*z;
        dst[1728 + p*36 + h*3 + 0] = gx;
        dst[1728 + p*36 + h*3 + 1] = gy;
        dst[1728 + p*36 + h*3 + 2] = gz;
        dst[2016 + p*12 + h] = sqrtf(gx*gx + gy*gy + gz*gz);
    }
}

// ---------------- kernel 8: o_pair (second pair pass) ----------------
__global__ void __launch_bounds__(128) k_opair(const float* __restrict__ pair) {
    __shared__ float as[H * S];     // 36 KB
    int i = blockIdx.x, t = threadIdx.x;
    for (int idx = t; idx < H * S; idx += 128) as[idx] = g_asum[idx];
    __syncthreads();
    const float* pb = pair + (size_t)i * S * CP + t;   // channel c = t
    float acc[H] = {};
    for (int k = 0; k < S; k += 4) {
        float p0 = pb[(size_t)(k + 0) * CP];
        float p1 = pb[(size_t)(k + 1) * CP];
        float p2 = pb[(size_t)(k + 2) * CP];
        float p3 = pb[(size_t)(k + 3) * CP];
        #pragma unroll
        for (int h = 0; h < H; h++)
            acc[h] += as[h*S + k] * p0 + as[h*S + k+1] * p1
                    + as[h*S + k+2] * p2 + as[h*S + k+3] * p3;
    }
    #pragma unroll
    for (int h = 0; h < H; h++)
        g_attn[i * FOUT + 192 + h * CP + t] = acc[h];
}

// ---------------- kernel 9: final GEMM attn[768,2112] @ Wo^T + bo ----------------
__global__ void __launch_bounds__(256) k_out(const float* __restrict__ Wo,
                                             const float* __restrict__ bo,
                                             float* __restrict__ out) {
    __shared__ float As[32 * 65];   // stores As[k][m]
    __shared__ float Bs[32 * 65];   // stores Bs[k][n]
    int i0 = blockIdx.x * 64, n0 = blockIdx.y * 64;
    int t = threadIdx.x, tx = t % 16, ty = t / 16;
    float acc[4][4] = {};
    for (int kc = 0; kc < FOUT; kc += 32) {
        __syncthreads();
        for (int idx = t; idx < 64 * 32; idx += 256) {
            int r = idx >> 5, kk = idx & 31;
            As[kk * 65 + r] = g_attn[(i0 + r) * FOUT + kc + kk];
            Bs[kk * 65 + r] = Wo[(n0 + r) * FOUT + kc + kk];
        }
        __syncthreads();
        for (int kk = 0; kk < 32; kk++) {
            float a4[4], b4[4];
            #pragma unroll
            for (int r = 0; r < 4; r++) {
                a4[r] = As[kk * 65 + ty * 4 + r];
                b4[r] = Bs[kk * 65 + tx * 4 + r];
            }
            #pragma unroll
            for (int r = 0; r < 4; r++)
                #pragma unroll
                for (int c = 0; c < 4; c++)
                    acc[r][c] += a4[r] * b4[c];
        }
    }
    #pragma unroll
    for (int r = 0; r < 4; r++)
        #pragma unroll
        for (int c = 0; c < 4; c++)
            out[(i0 + ty * 4 + r) * CS + n0 + tx * 4 + c] = acc[r][c] + bo[n0 + tx * 4 + c];
}

// ---------------- launch ----------------
extern "C" void kernel_launch(void* const* d_in, const int* in_sizes, int n_in,
                              void* d_out, int out_size) {
    const float* single = (const float*)d_in[0];
    const float* pair   = (const float*)d_in[1];
    const float* rot    = (const float*)d_in[2];
    const float* trans  = (const float*)d_in[3];
    const float* Wq     = (const float*)d_in[4];
    const float* Wk     = (const float*)d_in[5];
    const float* Wv     = (const float*)d_in[6];
    const float* Wqp    = (const float*)d_in[7];
    const float* Wkp    = (const float*)d_in[8];
    const float* Wvp    = (const float*)d_in[9];
    const float* Wb     = (const float*)d_in[10];
    const float* Wo     = (const float*)d_in[11];
    const float* bo     = (const float*)d_in[12];
    const float* gamma  = (const float*)d_in[13];
    float* out = (float*)d_out;

    k_proj<<<S / 16, 256>>>(single, Wq, Wk, Wv, Wqp, Wkp, Wvp);
    k_frames<<<(H * S + 255) / 256, 256>>>(rot, trans, gamma);
    k_logit<<<dim3(S / 64, S / 64, H), 256>>>();
    k_pairsm<<<S, 256>>>(pair, Wb);
    k_asum<<<dim3(S / 256, H), 256>>>();
    k_av<<<dim3(S / 64, H), 128>>>();
    k_invf<<<(H * S + 255) / 256, 256>>>(rot, trans);
    k_opair<<<S, 128>>>(pair);
    k_out<<<dim3(S / 64, CS / 64), 256>>>(Wo, bo, out);
}

// round 4
// speedup vs baseline: 1.2222x; 1.2222x over previous
#include <cuda_runtime.h>
#include <cuda_bf16.h>
#include <math.h>

#define S   768
#define CS  384
#define CP  128
#define E   16
#define PQ  4
#define PV  8
#define H   12
#define NCOL 1152            // per-residue projection columns: H*96
#define FOUT 2112            // H*(CP+E+PV*4)
#define SPLITK 3

#define SCALE_SINGLE 0.25f   // 1/sqrt(16)
#define SCALE_FRAME (-0.11785113019775793f)   // -1/sqrt(72)

typedef unsigned long long ull;

// packed f32x2 helpers
#define FFMA2(acc, a, b) asm volatile("fma.rn.f32x2 %0, %1, %2, %0;" : "+l"(acc) : "l"(a), "l"(b))
#define PACKDUP(out, x)  asm volatile("mov.b64 %0, {%1, %1};" : "=l"(out) : "f"(x))
#define UNPACK2(lo, hi, v) asm volatile("mov.b64 {%0, %1}, %2;" : "=f"(lo), "=f"(hi) : "l"(v))

// ---------------- scratch ----------------
__device__ float g_raw[S * NCOL];
__device__ float g_Qcat[H * S * 28];
__device__ float g_Kcat[H * S * 28];
__device__ float g_Vcat[H * S * 40];
__device__ float g_qn[H * S];
__device__ float g_kn[H * S];
__device__ float g_a[H * S * S];           // logits -> softmax in place (28.3MB)
__device__ float g_wp[S * S * H];          // pair bias [i][j][h] (28.3MB)
__device__ float g_asum[H * S];
__device__ float g_ol[H * S * PV * 3];
__device__ float g_attn[S * FOUT];
__device__ float g_part[SPLITK][S * CS];

// ---------------- kernel 1: projection GEMM ----------------
__device__ __forceinline__ const float* colptr(int j,
    const float* Wq, const float* Wk, const float* Wv,
    const float* Wqp, const float* Wkp, const float* Wvp) {
    int h = j / 96, off = j % 96;
    if (off < 16) return Wq  + (h * 16 + off) * CS;
    if (off < 32) return Wk  + (h * 16 + off - 16) * CS;
    if (off < 48) return Wv  + (h * 16 + off - 32) * CS;
    if (off < 60) return Wqp + (h * 12 + off - 48) * CS;
    if (off < 72) return Wkp + (h * 12 + off - 60) * CS;
    return Wvp + (h * 24 + off - 72) * CS;
}

__global__ void __launch_bounds__(256) k_proj(const float* __restrict__ x,
    const float* __restrict__ Wq, const float* __restrict__ Wk, const float* __restrict__ Wv,
    const float* __restrict__ Wqp, const float* __restrict__ Wkp, const float* __restrict__ Wvp) {
    __shared__ float xs[8 * CS];
    int s0 = blockIdx.x * 8;
    for (int idx = threadIdx.x; idx < 8 * CS; idx += 256)
        xs[idx] = x[s0 * CS + idx];
    __syncthreads();

    for (int j0 = threadIdx.x * 2; j0 < NCOL; j0 += 512) {
        const float* w0 = colptr(j0,     Wq, Wk, Wv, Wqp, Wkp, Wvp);
        const float* w1 = colptr(j0 + 1, Wq, Wk, Wv, Wqp, Wkp, Wvp);
        float acc0[8], acc1[8];
        #pragma unroll
        for (int s = 0; s < 8; s++) { acc0[s] = 0.f; acc1[s] = 0.f; }
        for (int kk = 0; kk < CS; kk += 4) {
            float4 wa = *(const float4*)(w0 + kk);
            float4 wb = *(const float4*)(w1 + kk);
            #pragma unroll
            for (int s = 0; s < 8; s++) {
                float4 xv = *(const float4*)&xs[s * CS + kk];
                acc0[s] += wa.x * xv.x + wa.y * xv.y + wa.z * xv.z + wa.w * xv.w;
                acc1[s] += wb.x * xv.x + wb.y * xv.y + wb.z * xv.z + wb.w * xv.w;
            }
        }
        #pragma unroll
        for (int s = 0; s < 8; s++) {
            g_raw[(s0 + s) * NCOL + j0]     = acc0[s];
            g_raw[(s0 + s) * NCOL + j0 + 1] = acc1[s];
        }
    }
}

// ---------------- kernel 2: frame apply + scale folding ----------------
__global__ void k_frames(const float* __restrict__ rot, const float* __restrict__ trans,
                         const float* __restrict__ gamma) {
    int idx = blockIdx.x * blockDim.x + threadIdx.x;
    if (idx >= H * S) return;
    int h = idx / S, s = idx % S;
    const float* R = rot + s * 9;
    float R00=R[0],R01=R[1],R02=R[2],R10=R[3],R11=R[4],R12=R[5],R20=R[6],R21=R[7],R22=R[8];
    float t0 = trans[s*3+0], t1 = trans[s*3+1], t2 = trans[s*3+2];
    float ch = SCALE_FRAME * log1pf(expf(gamma[h]));

    const float* raw = g_raw + s * NCOL + h * 96;
    float* qc = g_Qcat + (h * S + s) * 28;
    float* kc = g_Kcat + (h * S + s) * 28;
    float* vc = g_Vcat + (h * S + s) * 40;

    #pragma unroll
    for (int e = 0; e < 16; e++) {
        qc[e] = raw[e] * SCALE_SINGLE;
        kc[e] = raw[16 + e];
        vc[e] = raw[32 + e];
    }
    float qn = 0.f, kn = 0.f;
    float m2c = -2.f * ch;
    #pragma unroll
    for (int p = 0; p < 4; p++) {
        float x = raw[48+p*3], y = raw[48+p*3+1], z = raw[48+p*3+2];
        float lx = R00*x + R01*y + R02*z + t0;
        float ly = R10*x + R11*y + R12*z + t1;
        float lz = R20*x + R21*y + R22*z + t2;
        qc[16+p*3]   = lx * m2c;
        qc[16+p*3+1] = ly * m2c;
        qc[16+p*3+2] = lz * m2c;
        qn += lx*lx + ly*ly + lz*lz;

        x = raw[60+p*3]; y = raw[60+p*3+1]; z = raw[60+p*3+2];
        lx = R00*x + R01*y + R02*z + t0;
        ly = R10*x + R11*y + R12*z + t1;
        lz = R20*x + R21*y + R22*z + t2;
        kc[16+p*3]   = lx;
        kc[16+p*3+1] = ly;
        kc[16+p*3+2] = lz;
        kn += lx*lx + ly*ly + lz*lz;
    }
    #pragma unroll
    for (int p = 0; p < 8; p++) {
        float x = raw[72+p*3], y = raw[72+p*3+1], z = raw[72+p*3+2];
        vc[16+p*3]   = R00*x + R01*y + R02*z + t0;
        vc[16+p*3+1] = R10*x + R11*y + R12*z + t1;
        vc[16+p*3+2] = R20*x + R21*y + R22*z + t2;
    }
    g_qn[h * S + s] = ch * qn;
    g_kn[h * S + s] = ch * kn;
}

// ---------------- kernel 3: batched logit GEMM (K=28) ----------------
__global__ void __launch_bounds__(256) k_logit() {
    __shared__ float Qs[64 * 29], Ks[64 * 29], qns[64], kns[64];
    int h = blockIdx.z, i0 = blockIdx.y * 64, j0 = blockIdx.x * 64;
    int t = threadIdx.x;
    for (int idx = t; idx < 64 * 28; idx += 256) {
        int r = idx / 28, c = idx % 28;
        Qs[r * 29 + c] = g_Qcat[(h * S + i0 + r) * 28 + c];
        Ks[r * 29 + c] = g_Kcat[(h * S + j0 + r) * 28 + c];
    }
    if (t < 64) { qns[t] = g_qn[h * S + i0 + t]; kns[t] = g_kn[h * S + j0 + t]; }
    __syncthreads();
    int tx = t % 16, ty = t / 16;
    float acc[4][4] = {};
    for (int k = 0; k < 28; k++) {
        float aq[4], bk[4];
        #pragma unroll
        for (int r = 0; r < 4; r++) {
            aq[r] = Qs[(ty * 4 + r) * 29 + k];
            bk[r] = Ks[(tx * 4 + r) * 29 + k];
        }
        #pragma unroll
        for (int r = 0; r < 4; r++)
            #pragma unroll
            for (int c = 0; c < 4; c++)
                acc[r][c] += aq[r] * bk[c];
    }
    #pragma unroll
    for (int r = 0; r < 4; r++)
        #pragma unroll
        for (int c = 0; c < 4; c++)
            g_a[((size_t)h * S + i0 + ty * 4 + r) * S + j0 + tx * 4 + c] =
                acc[r][c] + qns[ty * 4 + r] + kns[tx * 4 + c];
}

// ---------------- kernel 4a: wp[i][j][h] = Wb[h] . pair[i,j,:]  (f32x2 GEMM) -------
// grid (S, 3): block = (row i, 256-j tile). K=128 in 4 chunks of 32.
__global__ void __launch_bounds__(256) k_wpair(const float* __restrict__ pair,
                                               const float* __restrict__ Wb) {
    __shared__ float As[32 * 260];     // [c][j], stride 260 (1040B, 16B aligned)
    __shared__ ull   WbPs[32 * 12];    // packed {w,w} per (c,h)
    int i = blockIdx.x, j0 = blockIdx.y * 256;
    int t = threadIdx.x;
    int j4 = (t & 63) * 4;
    int h0 = (t >> 6) * 3;

    ull acc[3][2] = {};
    const float4* pair4 = (const float4*)pair;

    for (int c0 = 0; c0 < 128; c0 += 32) {
        __syncthreads();
        // stage A: 256 j-rows x 32 ch, transposed
        #pragma unroll
        for (int l = 0; l < 8; l++) {
            int idx = t + l * 256;             // 2048 float4
            int j = idx >> 3, c4 = idx & 7;
            float4 v = pair4[((size_t)i * S + j0 + j) * 32 + (c0 >> 2) + c4];
            As[(c4 * 4 + 0) * 260 + j] = v.x;
            As[(c4 * 4 + 1) * 260 + j] = v.y;
            As[(c4 * 4 + 2) * 260 + j] = v.z;
            As[(c4 * 4 + 3) * 260 + j] = v.w;
        }
        // stage packed Wb: 32*12 = 384 entries, 256 threads -> strided loop (FIXED)
        for (int idx = t; idx < 384; idx += 256) {
            int c = idx / 12, h = idx % 12;
            float w = Wb[h * CP + c0 + c];
            ull wd; PACKDUP(wd, w);
            WbPs[c * 12 + h] = wd;
        }
        __syncthreads();

        #pragma unroll
        for (int c = 0; c < 32; c++) {
            ulonglong2 a = *(const ulonglong2*)&As[c * 260 + j4];  // {j0,j1},{j2,j3}
            ull w0 = WbPs[c * 12 + h0];
            ull w1 = WbPs[c * 12 + h0 + 1];
            ull w2 = WbPs[c * 12 + h0 + 2];
            FFMA2(acc[0][0], a.x, w0); FFMA2(acc[0][1], a.y, w0);
            FFMA2(acc[1][0], a.x, w1); FFMA2(acc[1][1], a.y, w1);
            FFMA2(acc[2][0], a.x, w2); FFMA2(acc[2][1], a.y, w2);
        }
    }
    #pragma unroll
    for (int hh = 0; hh < 3; hh++) {
        float v0, v1, v2, v3;
        UNPACK2(v0, v1, acc[hh][0]);
        UNPACK2(v2, v3, acc[hh][1]);
        size_t base = ((size_t)i * S + j0 + j4) * H + h0 + hh;
        g_wp[base]         = v0;
        g_wp[base + H]     = v1;
        g_wp[base + 2*H]   = v2;
        g_wp[base + 3*H]   = v3;
    }
}

// ---------------- kernel 4b: softmax over j (adds wp), warp per (head,row) --------
__global__ void __launch_bounds__(384) k_softmax() {
    __shared__ float wps[S * 13];
    int i = blockIdx.x, t = threadIdx.x, lane = t & 31, h = t >> 5;

    const float4* wp4 = (const float4*)(g_wp + (size_t)i * S * H);
    #pragma unroll
    for (int r = 0; r < 6; r++) {
        int idx = t + r * 384;                  // 2304 float4 total
        float4 v = wp4[idx];
        int l0 = idx * 4;
        wps[(l0 / 12) * 13 + (l0 % 12)]             = v.x;
        wps[((l0+1) / 12) * 13 + ((l0+1) % 12)]     = v.y;
        wps[((l0+2) / 12) * 13 + ((l0+2) % 12)]     = v.z;
        wps[((l0+3) / 12) * 13 + ((l0+3) % 12)]     = v.w;
    }
    __syncthreads();

    float* row = g_a + ((size_t)h * S + i) * S;
    float v[24];
    float m = -1e30f;
    #pragma unroll
    for (int r = 0; r < 24; r++) {
        int j = lane + 32 * r;
        v[r] = row[j] + wps[j * 13 + h];
        m = fmaxf(m, v[r]);
    }
    #pragma unroll
    for (int off = 16; off; off >>= 1) m = fmaxf(m, __shfl_xor_sync(0xffffffffu, m, off));
    float sum = 0.f;
    #pragma unroll
    for (int r = 0; r < 24; r++) { v[r] = __expf(v[r] - m); sum += v[r]; }
    #pragma unroll
    for (int off = 16; off; off >>= 1) sum += __shfl_xor_sync(0xffffffffu, sum, off);
    float inv = 1.f / sum;
    #pragma unroll
    for (int r = 0; r < 24; r++) row[lane + 32 * r] = v[r] * inv;
}

// ---------------- kernel 5: a_sum ----------------
__global__ void __launch_bounds__(256) k_asum() {
    int h = blockIdx.y;
    int k = blockIdx.x * 256 + threadIdx.x;
    const float* base = g_a + (size_t)h * S * S + k;
    float s0 = 0.f, s1 = 0.f, s2 = 0.f, s3 = 0.f;
    for (int i = 0; i < S; i += 4) {
        s0 += base[(size_t)(i + 0) * S];
        s1 += base[(size_t)(i + 1) * S];
        s2 += base[(size_t)(i + 2) * S];
        s3 += base[(size_t)(i + 3) * S];
    }
    g_asum[h * S + k] = (s0 + s1) + (s2 + s3);
}

// ---------------- kernel 6: per-head A @ Vcat (256 threads) ----------------
__global__ void __launch_bounds__(256) k_av() {
    __shared__ float As[64 * 65];
    __shared__ float Vs[64 * 41];
    int h = blockIdx.y, i0 = blockIdx.x * 64;
    int t = threadIdx.x;
    int ig = t >> 3, ng = t & 7;     // 32 i-pairs x 8 n-groups
    float acc[2][5] = {};

    for (int kc = 0; kc < S; kc += 64) {
        __syncthreads();
        for (int idx = t; idx < 64 * 64; idx += 256) {
            int r = idx >> 6, k = idx & 63;
            As[r * 65 + k] = g_a[((size_t)h * S + i0 + r) * S + kc + k];
        }
        for (int idx = t; idx < 64 * 40; idx += 256) {
            int r = idx / 40, n = idx % 40;
            Vs[r * 41 + n] = g_Vcat[(h * S + kc + r) * 40 + n];
        }
        __syncthreads();
        #pragma unroll 4
        for (int k = 0; k < 64; k++) {
            float a0 = As[(2 * ig) * 65 + k], a1 = As[(2 * ig + 1) * 65 + k];
            float vv[5];
            #pragma unroll
            for (int c = 0; c < 5; c++) vv[c] = Vs[k * 41 + ng + 8 * c];
            #pragma unroll
            for (int c = 0; c < 5; c++) {
                acc[0][c] += a0 * vv[c];
                acc[1][c] += a1 * vv[c];
            }
        }
    }
    #pragma unroll
    for (int r = 0; r < 2; r++) {
        int i = i0 + 2 * ig + r;
        #pragma unroll
        for (int c = 0; c < 5; c++) {
            int n = ng + 8 * c;
            float val = acc[r][c];
            if (n < 16) g_attn[i * FOUT + h * 16 + n] = val;
            else        g_ol[(h * S + i) * 24 + (n - 16)] = val;
        }
    }
}

// ---------------- kernel 7: inverse frame, points + norms ----------------
__global__ void k_invf(const float* __restrict__ rot, const float* __restrict__ trans) {
    int idx = blockIdx.x * blockDim.x + threadIdx.x;
    if (idx >= H * S) return;
    int h = idx / S, s = idx % S;
    const float* R = rot + s * 9;
    float R00=R[0],R01=R[1],R02=R[2],R10=R[3],R11=R[4],R12=R[5],R20=R[6],R21=R[7],R22=R[8];
    float t0 = trans[s*3+0], t1 = trans[s*3+1], t2 = trans[s*3+2];
    const float* ol = g_ol + (h * S + s) * 24;
    float* dst = g_attn + s * FOUT;
    #pragma unroll
    for (int p = 0; p < PV; p++) {
        float x = ol[p*3+0] - t0, y = ol[p*3+1] - t1, z = ol[p*3+2] - t2;
        float gx = R00*x + R10*y + R20*z;
        float gy = R01*x + R11*y + R21*z;
        float gz = R02*x + R12*y + R22*z;
        dst[1728 + p*36 + h*3 + 0] = gx;
        dst[1728 + p*36 + h*3 + 1] = gy;
        dst[1728 + p*36 + h*3 + 2] = gz;
        dst[2016 + p*12 + h] = sqrtf(gx*gx + gy*gy + gz*gz);
    }
}

// ---------------- kernel 8: o_pair[i][h][c] = sum_k asum[h][k] pair[i][k][c] ------
// grid 384 blocks (2 rows i each), 256 threads, f32x2 over c-pairs.
__global__ void __launch_bounds__(256) k_opair(const float* __restrict__ pair) {
    __shared__ float ps[2 * 32 * 128];     // [i][k][c]
    __shared__ ull   asumP[12 * 32];       // {a,a} per (h,k)
    int i0 = blockIdx.x * 2;
    int t = threadIdx.x;
    int il = t >> 7;                 // 0/1 (uniform within warp)
    int cg = ((t >> 2) & 31) * 4;    // c base (4 consecutive)
    int h0 = (t & 3) * 3;            // 3 heads

    ull acc[3][2] = {};
    const float4* pair4 = (const float4*)pair;

    for (int k0 = 0; k0 < S; k0 += 32) {
        __syncthreads();
        #pragma unroll
        for (int l = 0; l < 8; l++) {
            int idx = t + l * 256;             // 2048 float4
            int ii = idx >> 10, rem = idx & 1023;
            int k = rem >> 5, c4 = rem & 31;
            float4 v = pair4[((size_t)(i0 + ii) * S + k0 + k) * 32 + c4];
            *(float4*)&ps[(ii * 32 + k) * 128 + c4 * 4] = v;
        }
        // stage packed a_sum: 12*32 = 384 entries, 256 threads -> strided loop (FIXED)
        for (int idx = t; idx < 384; idx += 256) {
            int h = idx >> 5, k = idx & 31;
            float a = g_asum[h * S + k0 + k];
            ull ad; PACKDUP(ad, a);
            asumP[h * 32 + k] = ad;
        }
        __syncthreads();

        #pragma unroll
        for (int k = 0; k < 32; k++) {
            ulonglong2 p = *(const ulonglong2*)&ps[(il * 32 + k) * 128 + cg];
            ull a0 = asumP[h0 * 32 + k];
            ull a1 = asumP[(h0 + 1) * 32 + k];
            ull a2 = asumP[(h0 + 2) * 32 + k];
            FFMA2(acc[0][0], p.x, a0); FFMA2(acc[0][1], p.y, a0);
            FFMA2(acc[1][0], p.x, a1); FFMA2(acc[1][1], p.y, a1);
            FFMA2(acc[2][0], p.x, a2); FFMA2(acc[2][1], p.y, a2);
        }
    }
    int i = i0 + il;
    #pragma unroll
    for (int hh = 0; hh < 3; hh++) {
        float4 o;
        UNPACK2(o.x, o.y, acc[hh][0]);
        UNPACK2(o.z, o.w, acc[hh][1]);
        *(float4*)&g_attn[i * FOUT + 192 + (h0 + hh) * CP + cg] = o;
    }
}

// ---------------- kernel 9: split-K final GEMM -> partials ----------------
__global__ void __launch_bounds__(256) k_out(const float* __restrict__ Wo) {
    __shared__ float As[32 * 68];   // [kk][m]
    __shared__ float Bs[32 * 68];   // [kk][n]
    int i0 = blockIdx.x * 64, n0 = blockIdx.y * 64;
    int kb = blockIdx.z * (FOUT / SPLITK);
    int ke = kb + (FOUT / SPLITK);
    int t = threadIdx.x, tx = t % 16, ty = t / 16;
    ull acc[4][2] = {};
    for (int kc = kb; kc < ke; kc += 32) {
        __syncthreads();
        for (int idx = t; idx < 64 * 32; idx += 256) {
            int m = idx >> 5, kk = idx & 31;
            As[kk * 68 + m] = g_attn[(i0 + m) * FOUT + kc + kk];
            Bs[kk * 68 + m] = Wo[(n0 + m) * FOUT + kc + kk];
        }
        __syncthreads();
        #pragma unroll 4
        for (int kk = 0; kk < 32; kk++) {
            float4 am = *(const float4*)&As[kk * 68 + ty * 4];
            ulonglong2 bp = *(const ulonglong2*)&Bs[kk * 68 + tx * 4];
            ull a0, a1, a2, a3;
            PACKDUP(a0, am.x); PACKDUP(a1, am.y); PACKDUP(a2, am.z); PACKDUP(a3, am.w);
            FFMA2(acc[0][0], a0, bp.x); FFMA2(acc[0][1], a0, bp.y);
            FFMA2(acc[1][0], a1, bp.x); FFMA2(acc[1][1], a1, bp.y);
            FFMA2(acc[2][0], a2, bp.x); FFMA2(acc[2][1], a2, bp.y);
            FFMA2(acc[3][0], a3, bp.x); FFMA2(acc[3][1], a3, bp.y);
        }
    }
    float* dst = g_part[blockIdx.z];
    #pragma unroll
    for (int r = 0; r < 4; r++) {
        float4 o;
        UNPACK2(o.x, o.y, acc[r][0]);
        UNPACK2(o.z, o.w, acc[r][1]);
        *(float4*)&dst[(i0 + ty * 4 + r) * CS + n0 + tx * 4] = o;
    }
}

__global__ void __launch_bounds__(256) k_fin(const float* __restrict__ bo,
                                             float* __restrict__ out) {
    int idx = blockIdx.x * 256 + threadIdx.x;   // 294912 elems
    int n = idx % CS;
    out[idx] = bo[n] + g_part[0][idx] + g_part[1][idx] + g_part[2][idx];
}

// ---------------- launch ----------------
extern "C" void kernel_launch(void* const* d_in, const int* in_sizes, int n_in,
                              void* d_out, int out_size) {
    const float* single = (const float*)d_in[0];
    const float* pair   = (const float*)d_in[1];
    const float* rot    = (const float*)d_in[2];
    const float* trans  = (const float*)d_in[3];
    const float* Wq     = (const float*)d_in[4];
    const float* Wk     = (const float*)d_in[5];
    const float* Wv     = (const float*)d_in[6];
    const float* Wqp    = (const float*)d_in[7];
    const float* Wkp    = (const float*)d_in[8];
    const float* Wvp    = (const float*)d_in[9];
    const float* Wb     = (const float*)d_in[10];
    const float* Wo     = (const float*)d_in[11];
    const float* bo     = (const float*)d_in[12];
    const float* gamma  = (const float*)d_in[13];
    float* out = (float*)d_out;

    k_proj<<<S / 8, 256>>>(single, Wq, Wk, Wv, Wqp, Wkp, Wvp);
    k_frames<<<(H * S + 255) / 256, 256>>>(rot, trans, gamma);
    k_logit<<<dim3(S / 64, S / 64, H), 256>>>();
    k_wpair<<<dim3(S, 3), 256>>>(pair, Wb);
    k_softmax<<<S, 384>>>();
    k_asum<<<dim3(S / 256, H), 256>>>();
    k_av<<<dim3(S / 64, H), 256>>>();
    k_invf<<<(H * S + 255) / 256, 256>>>(rot, trans);
    k_opair<<<S / 2, 256>>>(pair);
    k_out<<<dim3(S / 64, CS / 64, SPLITK), 256>>>(Wo);
    k_fin<<<(S * CS) / 256, 256>>>(bo, out);
}

// round 5
// speedup vs baseline: 1.3385x; 1.0952x over previous
#include <cuda_runtime.h>
#include <cuda_bf16.h>
#include <math.h>

#define S   768
#define CS  384
#define CP  128
#define E   16
#define PQ  4
#define PV  8
#define H   12
#define NCOL 1152            // per-residue projection columns: H*96
#define FOUT 2112            // H*(CP+E+PV*4)
#define SPLITK 3

#define SCALE_SINGLE 0.25f   // 1/sqrt(16)
#define SCALE_FRAME (-0.11785113019775793f)   // -1/sqrt(72)

typedef unsigned long long ull;

// packed f32x2 helpers
#define FFMA2(acc, a, b) asm volatile("fma.rn.f32x2 %0, %1, %2, %0;" : "+l"(acc) : "l"(a), "l"(b))
#define PACKDUP(out, x)  asm volatile("mov.b64 %0, {%1, %1};" : "=l"(out) : "f"(x))
#define UNPACK2(lo, hi, v) asm volatile("mov.b64 {%0, %1}, %2;" : "=f"(lo), "=f"(hi) : "l"(v))

// ---------------- scratch ----------------
__device__ float g_raw[S * NCOL];
__device__ float g_Qcat[H * S * 28];
__device__ float g_Kcat[H * S * 28];
__device__ float g_Vcat[H * S * 40];
__device__ float g_qn[H * S];
__device__ float g_kn[H * S];
__device__ float g_a[H * S * S];           // logits -> softmax in place (28.3MB)
__device__ float g_wp[S * H * S];          // pair bias [i][h][j] (28.3MB)
__device__ float g_asum[H * S];
__device__ float g_ol[H * S * PV * 3];
__device__ float g_attn[S * FOUT];
__device__ float g_part[SPLITK][S * CS];

// ---------------- kernel 1: projection GEMM ----------------
__device__ __forceinline__ const float* colptr(int j,
    const float* Wq, const float* Wk, const float* Wv,
    const float* Wqp, const float* Wkp, const float* Wvp) {
    int h = j / 96, off = j % 96;
    if (off < 16) return Wq  + (h * 16 + off) * CS;
    if (off < 32) return Wk  + (h * 16 + off - 16) * CS;
    if (off < 48) return Wv  + (h * 16 + off - 32) * CS;
    if (off < 60) return Wqp + (h * 12 + off - 48) * CS;
    if (off < 72) return Wkp + (h * 12 + off - 60) * CS;
    return Wvp + (h * 24 + off - 72) * CS;
}

// grid (96, 2) x 288 threads: 8 s-rows, 576-column half, exactly 2 cols/thread
__global__ void __launch_bounds__(288) k_proj(const float* __restrict__ x,
    const float* __restrict__ Wq, const float* __restrict__ Wk, const float* __restrict__ Wv,
    const float* __restrict__ Wqp, const float* __restrict__ Wkp, const float* __restrict__ Wvp) {
    __shared__ float xs[8 * CS];
    int s0 = blockIdx.x * 8;
    int j0 = blockIdx.y * 576 + threadIdx.x * 2;
    for (int idx = threadIdx.x; idx < 8 * CS; idx += 288)
        xs[idx] = x[s0 * CS + idx];
    __syncthreads();

    const float* w0 = colptr(j0,     Wq, Wk, Wv, Wqp, Wkp, Wvp);
    const float* w1 = colptr(j0 + 1, Wq, Wk, Wv, Wqp, Wkp, Wvp);
    float acc0[8], acc1[8];
    #pragma unroll
    for (int s = 0; s < 8; s++) { acc0[s] = 0.f; acc1[s] = 0.f; }
    for (int kk = 0; kk < CS; kk += 4) {
        float4 wa = *(const float4*)(w0 + kk);
        float4 wb = *(const float4*)(w1 + kk);
        #pragma unroll
        for (int s = 0; s < 8; s++) {
            float4 xv = *(const float4*)&xs[s * CS + kk];
            acc0[s] += wa.x * xv.x + wa.y * xv.y + wa.z * xv.z + wa.w * xv.w;
            acc1[s] += wb.x * xv.x + wb.y * xv.y + wb.z * xv.z + wb.w * xv.w;
        }
    }
    #pragma unroll
    for (int s = 0; s < 8; s++) {
        g_raw[(s0 + s) * NCOL + j0]     = acc0[s];
        g_raw[(s0 + s) * NCOL + j0 + 1] = acc1[s];
    }
}

// ---------------- kernel 2: frame apply + scale folding ----------------
__global__ void k_frames(const float* __restrict__ rot, const float* __restrict__ trans,
                         const float* __restrict__ gamma) {
    int idx = blockIdx.x * blockDim.x + threadIdx.x;
    if (idx >= H * S) return;
    int h = idx / S, s = idx % S;
    const float* R = rot + s * 9;
    float R00=R[0],R01=R[1],R02=R[2],R10=R[3],R11=R[4],R12=R[5],R20=R[6],R21=R[7],R22=R[8];
    float t0 = trans[s*3+0], t1 = trans[s*3+1], t2 = trans[s*3+2];
    float ch = SCALE_FRAME * log1pf(expf(gamma[h]));

    const float* raw = g_raw + s * NCOL + h * 96;
    float* qc = g_Qcat + (h * S + s) * 28;
    float* kc = g_Kcat + (h * S + s) * 28;
    float* vc = g_Vcat + (h * S + s) * 40;

    #pragma unroll
    for (int e = 0; e < 16; e++) {
        qc[e] = raw[e] * SCALE_SINGLE;
        kc[e] = raw[16 + e];
        vc[e] = raw[32 + e];
    }
    float qn = 0.f, kn = 0.f;
    float m2c = -2.f * ch;
    #pragma unroll
    for (int p = 0; p < 4; p++) {
        float x = raw[48+p*3], y = raw[48+p*3+1], z = raw[48+p*3+2];
        float lx = R00*x + R01*y + R02*z + t0;
        float ly = R10*x + R11*y + R12*z + t1;
        float lz = R20*x + R21*y + R22*z + t2;
        qc[16+p*3]   = lx * m2c;
        qc[16+p*3+1] = ly * m2c;
        qc[16+p*3+2] = lz * m2c;
        qn += lx*lx + ly*ly + lz*lz;

        x = raw[60+p*3]; y = raw[60+p*3+1]; z = raw[60+p*3+2];
        lx = R00*x + R01*y + R02*z + t0;
        ly = R10*x + R11*y + R12*z + t1;
        lz = R20*x + R21*y + R22*z + t2;
        kc[16+p*3]   = lx;
        kc[16+p*3+1] = ly;
        kc[16+p*3+2] = lz;
        kn += lx*lx + ly*ly + lz*lz;
    }
    #pragma unroll
    for (int p = 0; p < 8; p++) {
        float x = raw[72+p*3], y = raw[72+p*3+1], z = raw[72+p*3+2];
        vc[16+p*3]   = R00*x + R01*y + R02*z + t0;
        vc[16+p*3+1] = R10*x + R11*y + R12*z + t1;
        vc[16+p*3+2] = R20*x + R21*y + R22*z + t2;
    }
    g_qn[h * S + s] = ch * qn;
    g_kn[h * S + s] = ch * kn;
}

// ---------------- kernel 3: batched logit GEMM (K=28) ----------------
__global__ void __launch_bounds__(256) k_logit() {
    __shared__ float Qs[64 * 29], Ks[64 * 29], qns[64], kns[64];
    int h = blockIdx.z, i0 = blockIdx.y * 64, j0 = blockIdx.x * 64;
    int t = threadIdx.x;
    for (int idx = t; idx < 64 * 28; idx += 256) {
        int r = idx / 28, c = idx % 28;
        Qs[r * 29 + c] = g_Qcat[(h * S + i0 + r) * 28 + c];
        Ks[r * 29 + c] = g_Kcat[(h * S + j0 + r) * 28 + c];
    }
    if (t < 64) { qns[t] = g_qn[h * S + i0 + t]; kns[t] = g_kn[h * S + j0 + t]; }
    __syncthreads();
    int tx = t % 16, ty = t / 16;
    float acc[4][4] = {};
    for (int k = 0; k < 28; k++) {
        float aq[4], bk[4];
        #pragma unroll
        for (int r = 0; r < 4; r++) {
            aq[r] = Qs[(ty * 4 + r) * 29 + k];
            bk[r] = Ks[(tx * 4 + r) * 29 + k];
        }
        #pragma unroll
        for (int r = 0; r < 4; r++)
            #pragma unroll
            for (int c = 0; c < 4; c++)
                acc[r][c] += aq[r] * bk[c];
    }
    #pragma unroll
    for (int r = 0; r < 4; r++)
        #pragma unroll
        for (int c = 0; c < 4; c++)
            g_a[((size_t)h * S + i0 + ty * 4 + r) * S + j0 + tx * 4 + c] =
                acc[r][c] + qns[ty * 4 + r] + kns[tx * 4 + c];
}

// ---------------- kernel 4a: wp[i][h][j] = Wb[h] . pair[i,j,:] ----------------
// One j per thread; swizzled 128B-row pair tile; Wb via LDS broadcast; K-paired f32x2.
__global__ void __launch_bounds__(256) k_wpair(const float* __restrict__ pair,
                                               const float* __restrict__ Wb) {
    __shared__ float ps[256 * 32];      // [j][32c] swizzled in 16B blocks (32KB)
    __shared__ float wbs[12 * 32];      // Wb chunk [h][32c]
    int i = blockIdx.x, j0 = blockIdx.y * 256;
    int t = threadIdx.x;

    ull acc[12] = {};
    const float4* pair4 = (const float4*)pair;

    for (int c0 = 0; c0 < 128; c0 += 32) {
        __syncthreads();
        #pragma unroll
        for (int l = 0; l < 8; l++) {
            int idx = t + l * 256;            // 2048 float4
            int j = idx >> 3, c4 = idx & 7;
            float4 v = pair4[((size_t)i * S + j0 + j) * 32 + (c0 >> 2) + c4];
            int blk = j * 8 + (c4 ^ (j & 7));
            *(float4*)&ps[blk * 4] = v;
        }
        for (int idx = t; idx < 384; idx += 256)
            wbs[idx] = Wb[(idx >> 5) * CP + c0 + (idx & 31)];
        __syncthreads();

        #pragma unroll
        for (int c4 = 0; c4 < 8; c4++) {
            int blk = t * 8 + (c4 ^ (t & 7));
            ulonglong2 pv = *(const ulonglong2*)&ps[blk * 4];
            #pragma unroll
            for (int h = 0; h < 12; h++) {
                ulonglong2 wb = *(const ulonglong2*)&wbs[h * 32 + c4 * 4];
                FFMA2(acc[h], pv.x, wb.x);
                FFMA2(acc[h], pv.y, wb.y);
            }
        }
    }
    #pragma unroll
    for (int h = 0; h < 12; h++) {
        float lo, hi; UNPACK2(lo, hi, acc[h]);
        g_wp[((size_t)i * H + h) * S + j0 + t] = lo + hi;
    }
}

// ---------------- kernel 4b: softmax over j (adds wp), warp per (head,row) --------
// No smem, no block sync: both g_a row and g_wp row are contiguous.
__global__ void __launch_bounds__(384) k_softmax() {
    int i = blockIdx.x, lane = threadIdx.x & 31, h = threadIdx.x >> 5;

    float4* row = (float4*)(g_a + ((size_t)h * S + i) * S);
    const float4* wr = (const float4*)(g_wp + ((size_t)i * H + h) * S);

    float4 v[6];
    float m = -1e30f;
    #pragma unroll
    for (int r = 0; r < 6; r++) {
        float4 a = row[r * 32 + lane];
        float4 w = wr[r * 32 + lane];
        v[r].x = a.x + w.x; v[r].y = a.y + w.y;
        v[r].z = a.z + w.z; v[r].w = a.w + w.w;
        m = fmaxf(m, fmaxf(fmaxf(v[r].x, v[r].y), fmaxf(v[r].z, v[r].w)));
    }
    #pragma unroll
    for (int off = 16; off; off >>= 1) m = fmaxf(m, __shfl_xor_sync(0xffffffffu, m, off));
    float sum = 0.f;
    #pragma unroll
    for (int r = 0; r < 6; r++) {
        v[r].x = __expf(v[r].x - m); v[r].y = __expf(v[r].y - m);
        v[r].z = __expf(v[r].z - m); v[r].w = __expf(v[r].w - m);
        sum += (v[r].x + v[r].y) + (v[r].z + v[r].w);
    }
    #pragma unroll
    for (int off = 16; off; off >>= 1) sum += __shfl_xor_sync(0xffffffffu, sum, off);
    float inv = 1.f / sum;
    #pragma unroll
    for (int r = 0; r < 6; r++) {
        v[r].x *= inv; v[r].y *= inv; v[r].z *= inv; v[r].w *= inv;
        row[r * 32 + lane] = v[r];
    }
}

// ---------------- kernel 5: a_sum ----------------
__global__ void __launch_bounds__(256) k_asum() {
    int h = blockIdx.y;
    int k = blockIdx.x * 256 + threadIdx.x;
    const float* base = g_a + (size_t)h * S * S + k;
    float s0 = 0.f, s1 = 0.f, s2 = 0.f, s3 = 0.f;
    for (int i = 0; i < S; i += 4) {
        s0 += base[(size_t)(i + 0) * S];
        s1 += base[(size_t)(i + 1) * S];
        s2 += base[(size_t)(i + 2) * S];
        s3 += base[(size_t)(i + 3) * S];
    }
    g_asum[h * S + k] = (s0 + s1) + (s2 + s3);
}

// ---------------- kernel 6: per-head A @ Vcat (256 threads) ----------------
__global__ void __launch_bounds__(256) k_av() {
    __shared__ float As[64 * 65];
    __shared__ float Vs[64 * 41];
    int h = blockIdx.y, i0 = blockIdx.x * 64;
    int t = threadIdx.x;
    int ig = t >> 3, ng = t & 7;     // 32 i-pairs x 8 n-groups
    float acc[2][5] = {};

    for (int kc = 0; kc < S; kc += 64) {
        __syncthreads();
        for (int idx = t; idx < 64 * 64; idx += 256) {
            int r = idx >> 6, k = idx & 63;
            As[r * 65 + k] = g_a[((size_t)h * S + i0 + r) * S + kc + k];
        }
        for (int idx = t; idx < 64 * 40; idx += 256) {
            int r = idx / 40, n = idx % 40;
            Vs[r * 41 + n] = g_Vcat[(h * S + kc + r) * 40 + n];
        }
        __syncthreads();
        #pragma unroll 4
        for (int k = 0; k < 64; k++) {
            float a0 = As[(2 * ig) * 65 + k], a1 = As[(2 * ig + 1) * 65 + k];
            float vv[5];
            #pragma unroll
            for (int c = 0; c < 5; c++) vv[c] = Vs[k * 41 + ng + 8 * c];
            #pragma unroll
            for (int c = 0; c < 5; c++) {
                acc[0][c] += a0 * vv[c];
                acc[1][c] += a1 * vv[c];
            }
        }
    }
    #pragma unroll
    for (int r = 0; r < 2; r++) {
        int i = i0 + 2 * ig + r;
        #pragma unroll
        for (int c = 0; c < 5; c++) {
            int n = ng + 8 * c;
            float val = acc[r][c];
            if (n < 16) g_attn[i * FOUT + h * 16 + n] = val;
            else        g_ol[(h * S + i) * 24 + (n - 16)] = val;
        }
    }
}

// ---------------- kernel 7: inverse frame, points + norms ----------------
__global__ void k_invf(const float* __restrict__ rot, const float* __restrict__ trans) {
    int idx = blockIdx.x * blockDim.x + threadIdx.x;
    if (idx >= H * S) return;
    int h = idx / S, s = idx % S;
    const float* R = rot + s * 9;
    float R00=R[0],R01=R[1],R02=R[2],R10=R[3],R11=R[4],R12=R[5],R20=R[6],R21=R[7],R22=R[8];
    float t0 = trans[s*3+0], t1 = trans[s*3+1], t2 = trans[s*3+2];
    const float* ol = g_ol + (h * S + s) * 24;
    float* dst = g_attn + s * FOUT;
    #pragma unroll
    for (int p = 0; p < PV; p++) {
        float x = ol[p*3+0] - t0, y = ol[p*3+1] - t1, z = ol[p*3+2] - t2;
        float gx = R00*x + R10*y + R20*z;
        float gy = R01*x + R11*y + R21*z;
        float gz = R02*x + R12*y + R22*z;
        dst[1728 + p*36 + h*3 + 0] = gx;
        dst[1728 + p*36 + h*3 + 1] = gy;
        dst[1728 + p*36 + h*3 + 2] = gz;
        dst[2016 + p*12 + h] = sqrtf(gx*gx + gy*gy + gz*gz);
    }
}

// ---------------- kernel 8: o_pair[i][h][c] = sum_k asum[h][k] pair[i][k][c] ------
__global__ void __launch_bounds__(256) k_opair(const float* __restrict__ pair) {
    __shared__ float ps[2 * 32 * 128];     // [i][k][c]
    __shared__ ull   asumP[12 * 32];       // {a,a} per (h,k)
    int i0 = blockIdx.x * 2;
    int t = threadIdx.x;
    int il = t >> 7;                 // 0/1 (uniform within warp)
    int cg = ((t >> 2) & 31) * 4;    // c base (4 consecutive)
    int h0 = (t & 3) * 3;            // 3 heads

    ull acc[3][2] = {};
    const float4* pair4 = (const float4*)pair;

    for (int k0 = 0; k0 < S; k0 += 32) {
        __syncthreads();
        #pragma unroll
        for (int l = 0; l < 8; l++) {
            int idx = t + l * 256;             // 2048 float4
            int ii = idx >> 10, rem = idx & 1023;
            int k = rem >> 5, c4 = rem & 31;
            float4 v = pair4[((size_t)(i0 + ii) * S + k0 + k) * 32 + c4];
            *(float4*)&ps[(ii * 32 + k) * 128 + c4 * 4] = v;
        }
        for (int idx = t; idx < 384; idx += 256) {
            int h = idx >> 5, k = idx & 31;
            float a = g_asum[h * S + k0 + k];
            ull ad; PACKDUP(ad, a);
            asumP[h * 32 + k] = ad;
        }
        __syncthreads();

        #pragma unroll
        for (int k = 0; k < 32; k++) {
            ulonglong2 p = *(const ulonglong2*)&ps[(il * 32 + k) * 128 + cg];
            ull a0 = asumP[h0 * 32 + k];
            ull a1 = asumP[(h0 + 1) * 32 + k];
            ull a2 = asumP[(h0 + 2) * 32 + k];
            FFMA2(acc[0][0], p.x, a0); FFMA2(acc[0][1], p.y, a0);
            FFMA2(acc[1][0], p.x, a1); FFMA2(acc[1][1], p.y, a1);
            FFMA2(acc[2][0], p.x, a2); FFMA2(acc[2][1], p.y, a2);
        }
    }
    int i = i0 + il;
    #pragma unroll
    for (int hh = 0; hh < 3; hh++) {
        float4 o;
        UNPACK2(o.x, o.y, acc[hh][0]);
        UNPACK2(o.z, o.w, acc[hh][1]);
        *(float4*)&g_attn[i * FOUT + 192 + (h0 + hh) * CP + cg] = o;
    }
}

// ---------------- kernel 9: split-K final GEMM -> partials ----------------
__global__ void __launch_bounds__(256) k_out(const float* __restrict__ Wo) {
    __shared__ float As[32 * 68];   // [kk][m]
    __shared__ float Bs[32 * 68];   // [kk][n]
    int i0 = blockIdx.x * 64, n0 = blockIdx.y * 64;
    int kb = blockIdx.z * (FOUT / SPLITK);
    int ke = kb + (FOUT / SPLITK);
    int t = threadIdx.x, tx = t % 16, ty = t / 16;
    ull acc[4][2] = {};
    for (int kc = kb; kc < ke; kc += 32) {
        __syncthreads();
        for (int idx = t; idx < 64 * 32; idx += 256) {
            int m = idx >> 5, kk = idx & 31;
            As[kk * 68 + m] = g_attn[(i0 + m) * FOUT + kc + kk];
            Bs[kk * 68 + m] = Wo[(n0 + m) * FOUT + kc + kk];
        }
        __syncthreads();
        #pragma unroll 4
        for (int kk = 0; kk < 32; kk++) {
            float4 am = *(const float4*)&As[kk * 68 + ty * 4];
            ulonglong2 bp = *(const ulonglong2*)&Bs[kk * 68 + tx * 4];
            ull a0, a1, a2, a3;
            PACKDUP(a0, am.x); PACKDUP(a1, am.y); PACKDUP(a2, am.z); PACKDUP(a3, am.w);
            FFMA2(acc[0][0], a0, bp.x); FFMA2(acc[0][1], a0, bp.y);
            FFMA2(acc[1][0], a1, bp.x); FFMA2(acc[1][1], a1, bp.y);
            FFMA2(acc[2][0], a2, bp.x); FFMA2(acc[2][1], a2, bp.y);
            FFMA2(acc[3][0], a3, bp.x); FFMA2(acc[3][1], a3, bp.y);
        }
    }
    float* dst = g_part[blockIdx.z];
    #pragma unroll
    for (int r = 0; r < 4; r++) {
        float4 o;
        UNPACK2(o.x, o.y, acc[r][0]);
        UNPACK2(o.z, o.w, acc[r][1]);
        *(float4*)&dst[(i0 + ty * 4 + r) * CS + n0 + tx * 4] = o;
    }
}

__global__ void __launch_bounds__(256) k_fin(const float* __restrict__ bo,
                                             float* __restrict__ out) {
    int idx = blockIdx.x * 256 + threadIdx.x;   // 294912 elems
    int n = idx % CS;
    out[idx] = bo[n] + g_part[0][idx] + g_part[1][idx] + g_part[2][idx];
}

// ---------------- launch ----------------
extern "C" void kernel_launch(void* const* d_in, const int* in_sizes, int n_in,
                              void* d_out, int out_size) {
    const float* single = (const float*)d_in[0];
    const float* pair   = (const float*)d_in[1];
    const float* rot    = (const float*)d_in[2];
    const float* trans  = (const float*)d_in[3];
    const float* Wq     = (const float*)d_in[4];
    const float* Wk     = (const float*)d_in[5];
    const float* Wv     = (const float*)d_in[6];
    const float* Wqp    = (const float*)d_in[7];
    const float* Wkp    = (const float*)d_in[8];
    const float* Wvp    = (const float*)d_in[9];
    const float* Wb     = (const float*)d_in[10];
    const float* Wo     = (const float*)d_in[11];
    const float* bo     = (const float*)d_in[12];
    const float* gamma  = (const float*)d_in[13];
    float* out = (float*)d_out;

    k_proj<<<dim3(S / 8, 2), 288>>>(single, Wq, Wk, Wv, Wqp, Wkp, Wvp);
    k_frames<<<(H * S + 255) / 256, 256>>>(rot, trans, gamma);
    k_logit<<<dim3(S / 64, S / 64, H), 256>>>();
    k_wpair<<<dim3(S, 3), 256>>>(pair, Wb);
    k_softmax<<<S, 384>>>();
    k_asum<<<dim3(S / 256, H), 256>>>();
    k_av<<<dim3(S / 64, H), 256>>>();
    k_invf<<<(H * S + 255) / 256, 256>>>(rot, trans);
    k_opair<<<S / 2, 256>>>(pair);
    k_out<<<dim3(S / 64, CS / 64, SPLITK), 256>>>(Wo);
    k_fin<<<(S * CS) / 256, 256>>>(bo, out);
}